// round 2
// baseline (speedup 1.0000x reference)
#include <cuda_runtime.h>
#include <math.h>

#define NB 16
#define NN 2048
#define NK 20
#define NC 64

// ---- scratch (static __device__, allocation-free) ----
__device__ int   g_idx [NB*NN*NK];          // knn indices
__device__ float g_bxT [NB*NN*NC];          // (basis_W @ x) * act_g, n-major
__device__ float g_cst [NB*NN*NC];          // edge_g*((We2-We1)@x) + edge_be
__device__ float g_glfT[NB*NN*NK*32];       // glf transposed to (b,n,k,c)

// =====================================================================
// KNN: per (b,q) keep top-20 by pd = 2*<pq,pm> - |pq|^2 - |pm|^2 (excl self)
// Register-resident top-k: constant-indexed compare-swap bubble (no lmem).
// =====================================================================
__global__ void knn_kernel(const float* __restrict__ pos)
{
    __shared__ float4 sp[NN];
    const int b   = blockIdx.y;
    const int tid = threadIdx.x;
    const float* pb = pos + (size_t)b*3*NN;
    for (int m = tid; m < NN; m += blockDim.x) {
        float x = pb[m];
        float y = pb[NN + m];
        float z = pb[2*NN + m];
        sp[m] = make_float4(x, y, z, x*x + y*y + z*z);
    }
    __syncthreads();
    const int q = blockIdx.x * blockDim.x + tid;
    const float4 pq = sp[q];

    float tv[NK];
    int   ti[NK];
    #pragma unroll
    for (int i = 0; i < NK; i++) { tv[i] = -1e30f; ti[i] = 0; }

    #pragma unroll 1
    for (int m = 0; m < NN; m++) {
        if (m == q) continue;
        float4 pm = sp[m];
        float inner = pq.x*pm.x + pq.y*pm.y + pq.z*pm.z;
        float pd = 2.0f*inner - pq.w - pm.w;
        // strict >: on tie, existing (lower index) entry wins — matches lax.top_k
        if (pd > tv[NK-1]) {
            tv[NK-1] = pd; ti[NK-1] = m;
            #pragma unroll
            for (int i = NK-1; i > 0; i--) {
                // strict >: stops at equal values, keeping earlier index above
                if (tv[i] > tv[i-1]) {
                    float fv = tv[i-1]; tv[i-1] = tv[i]; tv[i] = fv;
                    int   iv = ti[i-1]; ti[i-1] = ti[i]; ti[i] = iv;
                }
            }
        }
    }
    int* op = g_idx + ((size_t)b*NN + q)*NK;
    #pragma unroll
    for (int i = 0; i < NK; i++) op[i] = ti[i];
}

// =====================================================================
// prep: bxT[p][c] = act_g[c] * sum_c' basis_W[c][c'] x[b][c'][n]
//       cst[p][o] = edge_g[o] * sum_c (We[o][64+c]-We[o][c]) x[b][c][n] + edge_be[o]
// =====================================================================
__global__ void prep_kernel(const float* __restrict__ x,
                            const float* __restrict__ basis_W,
                            const float* __restrict__ edge_W,
                            const float* __restrict__ act_g,
                            const float* __restrict__ edge_g,
                            const float* __restrict__ edge_be)
{
    __shared__ float sB[64*64];
    __shared__ float sD[64*64];
    __shared__ float sag[64], seg[64], seb[64];
    const int tid = threadIdx.x;
    for (int i = tid; i < 4096; i += blockDim.x) {
        sB[i] = basis_W[i];
        int o = i >> 6, c = i & 63;
        sD[i] = edge_W[o*128 + 64 + c] - edge_W[o*128 + c];
    }
    for (int i = tid; i < 64; i += blockDim.x) {
        sag[i] = act_g[i]; seg[i] = edge_g[i]; seb[i] = edge_be[i];
    }
    __syncthreads();

    const int p = blockIdx.x * blockDim.x + tid;     // b*NN + n
    const int b = p / NN, n = p % NN;
    const float* xp = x + (size_t)b*64*NN + n;
    float xv[64];
    #pragma unroll
    for (int c = 0; c < 64; c++) xv[c] = xp[(size_t)c*NN];

    float* bo = g_bxT + (size_t)p*64;
    #pragma unroll 4
    for (int o = 0; o < 64; o++) {
        float acc = 0.f;
        #pragma unroll
        for (int c = 0; c < 64; c++) acc += sB[o*64+c]*xv[c];
        bo[o] = acc * sag[o];
    }
    float* co = g_cst + (size_t)p*64;
    #pragma unroll 4
    for (int o = 0; o < 64; o++) {
        float acc = 0.f;
        #pragma unroll
        for (int c = 0; c < 64; c++) acc += sD[o*64+c]*xv[c];
        co[o] = acc*seg[o] + seb[o];
    }
}

// =====================================================================
// glf transpose: (B, 32, N*K) -> (B, N*K, 32)
// =====================================================================
__global__ void glf_tr_kernel(const float* __restrict__ glf)
{
    __shared__ float t[32][33];
    const int b    = blockIdx.y;
    const int col0 = blockIdx.x * 32;
    const float* in  = glf    + (size_t)b*32*NN*NK;
    float*       out = g_glfT + (size_t)b*NN*NK*32;
    const int tx = threadIdx.x, ty = threadIdx.y;
    #pragma unroll
    for (int r = ty; r < 32; r += 8)
        t[r][tx] = in[(size_t)r*(NN*NK) + col0 + tx];
    __syncthreads();
    #pragma unroll
    for (int r = ty; r < 32; r += 8)
        out[(size_t)(col0 + r)*32 + tx] = t[tx][r];
}

// =====================================================================
// main fused kernel: one thread per point (b,n), loop k=0..19
// mx[] and cst[] live in padded smem (stride 65 -> conflict-free) so the
// per-thread register footprint stays ~160 regs, zero local memory.
// =====================================================================
#define SMEM_FLOATS (8976 + 128*65 + 128*65)

__global__ void __launch_bounds__(128)
main_kernel(const float* __restrict__ appf,
            const float* __restrict__ dk_W1, const float* __restrict__ dk_b1,
            const float* __restrict__ dk_g1, const float* __restrict__ dk_be1,
            const float* __restrict__ dk_W2, const float* __restrict__ dk_b2,
            const float* __restrict__ act_b,
            const float* __restrict__ ff_W1, const float* __restrict__ ff_g1,
            const float* __restrict__ ff_be1, const float* __restrict__ ff_W2,
            const float* __restrict__ edge_W, const float* __restrict__ edge_g,
            float* __restrict__ out)
{
    extern __shared__ float sm[];
    float* sW1 = sm;           // 128  : dk_g1 folded dk_W1
    float* sb1 = sW1 + 128;    // 16
    float* sW2 = sb1 + 16;     // 512
    float* sb2 = sW2 + 512;    // 32
    float* sF1 = sb2 + 32;     // 2048 : ff_g1 folded ff_W1
    float* sbf = sF1 + 2048;   // 32   : ff_be1
    float* sF2 = sbf + 32;     // 2048
    float* sab = sF2 + 2048;   // 64   : act_b
    float* sWE = sab + 64;     // 4096 : edge_g folded edge_W[:, :64]
    float* scst= sWE + 4096;   // 128*65 padded per-thread cst
    float* smx = scst + 128*65;// 128*65 padded per-thread running max

    const int tid = threadIdx.x;
    for (int i = tid; i < 128;  i += 128) sW1[i] = dk_g1[i>>3] * dk_W1[i];
    if (tid < 16) sb1[tid] = dk_g1[tid]*dk_b1[tid] + dk_be1[tid];
    for (int i = tid; i < 512;  i += 128) sW2[i] = dk_W2[i];
    if (tid < 32) sb2[tid] = dk_b2[tid];
    for (int i = tid; i < 2048; i += 128) sF1[i] = ff_g1[i>>6]*ff_W1[i];
    if (tid < 32) sbf[tid] = ff_be1[tid];
    for (int i = tid; i < 2048; i += 128) sF2[i] = ff_W2[i];
    if (tid < 64) sab[tid] = act_b[tid];
    for (int i = tid; i < 4096; i += 128) {
        int o = i >> 6, c = i & 63;
        sWE[i] = edge_g[o]*edge_W[o*128 + c];
    }
    {   // stage this block's cst rows (coalesced read -> padded smem)
        const float* cb = g_cst + (size_t)blockIdx.x*128*64;
        for (int i = tid; i < 128*64; i += 128) {
            int t = i >> 6, o = i & 63;
            scst[t*65 + o] = cb[i];
        }
    }
    #pragma unroll
    for (int o = 0; o < 64; o++) smx[tid*65 + o] = -1e30f;
    __syncthreads();

    const int p = blockIdx.x*128 + tid;       // b*NN + n
    const int b = p >> 11;
    const int n = p & (NN-1);

    const int*   ip = g_idx  + (size_t)p*NK;
    const float* ap = appf   + (size_t)p*NK*8;
    const float* gl = g_glfT + (size_t)p*NK*32;

    #pragma unroll 1
    for (int k = 0; k < NK; k++) {
        // ---- appf features ----
        float a[8];
        {
            const float4* a4 = (const float4*)(ap + k*8);
            float4 v0 = a4[0], v1 = a4[1];
            a[0]=v0.x; a[1]=v0.y; a[2]=v0.z; a[3]=v0.w;
            a[4]=v1.x; a[5]=v1.y; a[6]=v1.z; a[7]=v1.w;
        }
        // ---- dk layer 1: 8 -> 16, relu(bn) ----
        float h[16];
        #pragma unroll
        for (int o = 0; o < 16; o++) {
            const float4* w = (const float4*)(sW1 + o*8);
            float4 w0 = w[0], w1 = w[1];
            float t = sb1[o];
            t += w0.x*a[0] + w0.y*a[1] + w0.z*a[2] + w0.w*a[3];
            t += w1.x*a[4] + w1.y*a[5] + w1.z*a[6] + w1.w*a[7];
            h[o] = fmaxf(t, 0.f);
        }
        // ---- dk layer 2: 16 -> 32 ; rif = [f32, glf32] ----
        float r[64];
        #pragma unroll
        for (int o = 0; o < 32; o++) {
            const float4* w = (const float4*)(sW2 + o*16);
            float t = sb2[o];
            #pragma unroll
            for (int c4 = 0; c4 < 4; c4++) {
                float4 wv = w[c4];
                t += wv.x*h[c4*4+0] + wv.y*h[c4*4+1] + wv.z*h[c4*4+2] + wv.w*h[c4*4+3];
            }
            r[o] = t;
        }
        {
            const float4* g4 = (const float4*)(gl + k*32);
            #pragma unroll
            for (int u = 0; u < 8; u++) {
                float4 v = g4[u];
                r[32+u*4+0]=v.x; r[32+u*4+1]=v.y; r[32+u*4+2]=v.z; r[32+u*4+3]=v.w;
            }
        }
        // ---- attention layer 1: 64 -> 32, leaky(bn) ----
        float att[32];
        #pragma unroll
        for (int o = 0; o < 32; o++) {
            const float4* w = (const float4*)(sF1 + o*64);
            float t = sbf[o];
            #pragma unroll
            for (int c4 = 0; c4 < 16; c4++) {
                float4 wv = w[c4];
                t += wv.x*r[c4*4+0] + wv.y*r[c4*4+1] + wv.z*r[c4*4+2] + wv.w*r[c4*4+3];
            }
            att[o] = (t > 0.f) ? t : 0.2f*t;
        }
        // ---- attention layer 2: 32 -> 64 sigmoid; gate; gather; relu(bn) ----
        const int j = ip[k];
        const float4* bx4 = (const float4*)(g_bxT + ((size_t)b*NN + j)*64);
        #pragma unroll
        for (int o4 = 0; o4 < 16; o4++) {
            float4 gv = bx4[o4];
            #pragma unroll
            for (int u = 0; u < 4; u++) {
                int o = o4*4 + u;
                const float4* w = (const float4*)(sF2 + o*32);
                float t = 0.f;
                #pragma unroll
                for (int c4 = 0; c4 < 8; c4++) {
                    float4 wv = w[c4];
                    t += wv.x*att[c4*4+0] + wv.y*att[c4*4+1] + wv.z*att[c4*4+2] + wv.w*att[c4*4+3];
                }
                float s = 1.0f/(1.0f + __expf(-t));
                float gg = (u == 0) ? gv.x : (u == 1) ? gv.y : (u == 2) ? gv.z : gv.w;
                r[o] = fmaxf((r[o]*s)*gg + sab[o], 0.f);
            }
        }
        // ---- edge layer (folded): out = leaky(WE@feat + cst), running max in smem ----
        #pragma unroll
        for (int o = 0; o < 64; o++) {
            const float4* w = (const float4*)(sWE + o*64);
            float t = scst[tid*65 + o];
            #pragma unroll
            for (int c4 = 0; c4 < 16; c4++) {
                float4 wv = w[c4];
                t += wv.x*r[c4*4+0] + wv.y*r[c4*4+1] + wv.z*r[c4*4+2] + wv.w*r[c4*4+3];
            }
            t = (t > 0.f) ? t : 0.2f*t;
            smx[tid*65 + o] = fmaxf(smx[tid*65 + o], t);
        }
    }
    float* op = out + ((size_t)b*64)*NN + n;
    #pragma unroll
    for (int o = 0; o < 64; o++) op[(size_t)o*NN] = smx[tid*65 + o];
}

// =====================================================================
extern "C" void kernel_launch(void* const* d_in, const int* in_sizes, int n_in,
                              void* d_out, int out_size)
{
    const float* pos     = (const float*)d_in[0];
    const float* x       = (const float*)d_in[1];
    const float* glf     = (const float*)d_in[2];
    const float* appf    = (const float*)d_in[3];
    const float* basis_W = (const float*)d_in[4];
    const float* dk_W1   = (const float*)d_in[5];
    const float* dk_b1   = (const float*)d_in[6];
    const float* dk_g1   = (const float*)d_in[7];
    const float* dk_be1  = (const float*)d_in[8];
    const float* dk_W2   = (const float*)d_in[9];
    const float* dk_b2   = (const float*)d_in[10];
    const float* act_g   = (const float*)d_in[11];
    const float* act_b   = (const float*)d_in[12];
    const float* ff_W1   = (const float*)d_in[13];
    const float* ff_g1   = (const float*)d_in[14];
    const float* ff_be1  = (const float*)d_in[15];
    const float* ff_W2   = (const float*)d_in[16];
    const float* edge_W  = (const float*)d_in[17];
    const float* edge_g  = (const float*)d_in[18];
    const float* edge_be = (const float*)d_in[19];
    float* out = (float*)d_out;

    knn_kernel<<<dim3(NN/256, NB), 256>>>(pos);
    prep_kernel<<<(NB*NN)/128, 128>>>(x, basis_W, edge_W, act_g, edge_g, edge_be);
    glf_tr_kernel<<<dim3((NN*NK)/32, NB), dim3(32, 8)>>>(glf);

    const int smem_bytes = SMEM_FLOATS * (int)sizeof(float);
    cudaFuncSetAttribute(main_kernel, cudaFuncAttributeMaxDynamicSharedMemorySize, smem_bytes);
    main_kernel<<<(NB*NN)/128, 128, smem_bytes>>>(appf, dk_W1, dk_b1, dk_g1, dk_be1,
                                                  dk_W2, dk_b2, act_b,
                                                  ff_W1, ff_g1, ff_be1, ff_W2,
                                                  edge_W, edge_g, out);
}

// round 3
// speedup vs baseline: 1.7945x; 1.7945x over previous
#include <cuda_runtime.h>
#include <math.h>

#define NB 16
#define NN 2048
#define NK 20
#define NC 64

// ---- scratch (static __device__, allocation-free) ----
__device__ int   g_idxT[NB*NK*NN];          // knn indices, [b][k][n]
__device__ float g_bxT [NB*NN*NC];          // act_g * (basis_W @ x), point-major [p][c]
__device__ float g_cst [NB*NN*NC];          // edge_g*((We2-We1)@x) + edge_be, [p][o]
__device__ float g_apT [NB*NK*8*NN];        // appf transposed to [b][k][c][n]
__device__ float g_glT [NB*NK*32*NN];       // glf  transposed to [b][k][c][n]

// =====================================================================
// KNN: per (b,q) top-20 by pd = 2<pq,pm> - |pq|^2 - |pm|^2 (excl self)
// =====================================================================
__global__ void knn_kernel(const float* __restrict__ pos)
{
    __shared__ float4 sp[NN];
    const int b   = blockIdx.y;
    const int tid = threadIdx.x;
    const float* pb = pos + (size_t)b*3*NN;
    for (int m = tid; m < NN; m += blockDim.x) {
        float x = pb[m], y = pb[NN + m], z = pb[2*NN + m];
        sp[m] = make_float4(x, y, z, x*x + y*y + z*z);
    }
    __syncthreads();
    const int q = blockIdx.x * blockDim.x + tid;
    const float4 pq = sp[q];

    float tv[NK]; int ti[NK];
    #pragma unroll
    for (int i = 0; i < NK; i++) { tv[i] = -1e30f; ti[i] = 0; }

    #pragma unroll 1
    for (int m = 0; m < NN; m++) {
        if (m == q) continue;
        float4 pm = sp[m];
        float pd = 2.0f*(pq.x*pm.x + pq.y*pm.y + pq.z*pm.z) - pq.w - pm.w;
        if (pd > tv[NK-1]) {
            tv[NK-1] = pd; ti[NK-1] = m;
            #pragma unroll
            for (int i = NK-1; i > 0; i--) {
                if (tv[i] > tv[i-1]) {       // strict: ties keep lower index first
                    float fv = tv[i-1]; tv[i-1] = tv[i]; tv[i] = fv;
                    int   iv = ti[i-1]; ti[i-1] = ti[i]; ti[i] = iv;
                }
            }
        }
    }
    #pragma unroll
    for (int i = 0; i < NK; i++)
        g_idxT[((size_t)b*NK + i)*NN + q] = ti[i];
}

// =====================================================================
// prep: g_bxT[p][c] = act_g[c] * (basis_W @ x)[c]
//       g_cst[p][o] = edge_g[o] * ((We2-We1)@x)[o] + edge_be[o]
// =====================================================================
__global__ void prep_kernel(const float* __restrict__ x,
                            const float* __restrict__ basis_W,
                            const float* __restrict__ edge_W,
                            const float* __restrict__ act_g,
                            const float* __restrict__ edge_g,
                            const float* __restrict__ edge_be)
{
    __shared__ float sB[64*64];
    __shared__ float sD[64*64];
    __shared__ float sag[64], seg[64], seb[64];
    const int tid = threadIdx.x;
    for (int i = tid; i < 4096; i += blockDim.x) {
        sB[i] = basis_W[i];
        int o = i >> 6, c = i & 63;
        sD[i] = edge_W[o*128 + 64 + c] - edge_W[o*128 + c];
    }
    for (int i = tid; i < 64; i += blockDim.x) {
        sag[i] = act_g[i]; seg[i] = edge_g[i]; seb[i] = edge_be[i];
    }
    __syncthreads();

    const int p = blockIdx.x * blockDim.x + tid;
    const int b = p / NN, n = p % NN;
    const float* xp = x + (size_t)b*64*NN + n;
    float xv[64];
    #pragma unroll
    for (int c = 0; c < 64; c++) xv[c] = xp[(size_t)c*NN];

    float* bo = g_bxT + (size_t)p*64;
    #pragma unroll 4
    for (int o = 0; o < 64; o++) {
        float acc = 0.f;
        #pragma unroll
        for (int c = 0; c < 64; c++) acc += sB[o*64+c]*xv[c];
        bo[o] = acc * sag[o];
    }
    float* co = g_cst + (size_t)p*64;
    #pragma unroll 4
    for (int o = 0; o < 64; o++) {
        float acc = 0.f;
        #pragma unroll
        for (int c = 0; c < 64; c++) acc += sD[o*64+c]*xv[c];
        co[o] = acc*seg[o] + seb[o];
    }
}

// =====================================================================
// appf transpose: (B,N,K,8) -> [b][k][c][n]
// block: 256 thr, tile = 32 n of one b. 5120 contiguous floats in, padded smem.
// =====================================================================
__global__ void ap_tr_kernel(const float* __restrict__ appf)
{
    __shared__ float s[32*161];
    const int b  = blockIdx.y;
    const int n0 = blockIdx.x * 32;
    const int tid = threadIdx.x;
    const float* in = appf + ((size_t)b*NN + n0) * (NK*8);
    #pragma unroll
    for (int u = 0; u < 20; u++) {
        int f = tid + u*256;                 // 5120 total
        int n = f / 160, r = f % 160;
        s[n*161 + r] = in[f];
    }
    __syncthreads();
    #pragma unroll
    for (int u = 0; u < 20; u++) {
        int f = tid + u*256;
        int row = f >> 5, n = f & 31;        // row = k*8+c
        g_apT[((size_t)b*NK*8 + row)*NN + n0 + n] = s[n*161 + row];
    }
}

// =====================================================================
// glf transpose: (B,32,N,K) -> [b][k][c][n]
// block: 256 thr, tile = (b, c, 64 n). 1280 contiguous floats in.
// =====================================================================
__global__ void glf_tr_kernel(const float* __restrict__ glf)
{
    __shared__ float s[64*21];
    const int n0 = blockIdx.x * 64;
    const int c  = blockIdx.y;
    const int b  = blockIdx.z;
    const int tid = threadIdx.x;
    const float* in = glf + (((size_t)b*32 + c)*NN + n0) * NK;
    #pragma unroll
    for (int u = 0; u < 5; u++) {
        int f = tid + u*256;                 // 1280 total
        int n = f / 20, k = f % 20;
        s[n*21 + k] = in[f];
    }
    __syncthreads();
    #pragma unroll
    for (int u = 0; u < 5; u++) {
        int f = tid + u*256;
        int k = f >> 6, n = f & 63;
        g_glT[(((size_t)b*NK + k)*32 + c)*NN + n0 + n] = s[n*21 + k];
    }
}

// =====================================================================
// main fused kernel: CTA = 256 threads, 128-point tile, k-loop inside.
// All layers as [out x 128] register-blocked GEMMs on smem tiles.
// =====================================================================
#define LEAKY(v) ((v) > 0.f ? (v) : 0.2f*(v))

__global__ void __launch_bounds__(256, 2)
main_kernel(const float* __restrict__ dk_W1, const float* __restrict__ dk_b1,
            const float* __restrict__ dk_g1, const float* __restrict__ dk_be1,
            const float* __restrict__ dk_W2, const float* __restrict__ dk_b2,
            const float* __restrict__ act_b,
            const float* __restrict__ ff_W1, const float* __restrict__ ff_g1,
            const float* __restrict__ ff_be1, const float* __restrict__ ff_W2,
            const float* __restrict__ edge_W, const float* __restrict__ edge_g,
            float* __restrict__ out)
{
    extern __shared__ float sm[];
    float* wW1t = sm;             // [8][16]   128
    float* wb1  = wW1t + 128;     // 16
    float* wW2t = wb1  + 16;      // [16][32]  512
    float* wb2  = wW2t + 512;     // 32
    float* wF1t = wb2  + 32;      // [64][32]  2048
    float* wbf  = wF1t + 2048;    // 32
    float* wF2t = wbf  + 32;      // [32][64]  2048
    float* wab  = wF2t + 2048;    // 64
    float* wWEt = wab  + 64;      // [64][64]  4096
    float* t_in = wWEt + 4096;    // [8][128]  1024
    float* t_h  = t_in + 1024;    // [16][128] 2048
    float* t_rif= t_h  + 2048;    // [64][128] 8192 (becomes feat in place)
    float* t_att= t_rif+ 8192;    // [32][128] 4096
    int*   s_idx= (int*)(t_att + 4096);   // 128

    const int tid = threadIdx.x;
    const int w   = tid >> 5;
    const int l   = tid & 31;
    const int p0  = l*4;
    const int b   = blockIdx.x >> 4;
    const int n0  = (blockIdx.x & 15) << 7;

    // ---- stage folded, transposed weights ----
    for (int i = tid; i < 128; i += 256) { int c=i>>4, o=i&15; wW1t[i] = dk_g1[o]*dk_W1[o*8+c]; }
    if (tid < 16) wb1[tid] = dk_g1[tid]*dk_b1[tid] + dk_be1[tid];
    for (int i = tid; i < 512; i += 256) { int c=i>>5, o=i&31; wW2t[i] = dk_W2[o*16+c]; }
    if (tid < 32) wb2[tid] = dk_b2[tid];
    for (int i = tid; i < 2048; i += 256) { int c=i>>5, o=i&31; wF1t[i] = ff_g1[o]*ff_W1[o*64+c]; }
    if (tid < 32) wbf[tid] = ff_be1[tid];
    for (int i = tid; i < 2048; i += 256) { int c=i>>6, o=i&63; wF2t[i] = ff_W2[o*32+c]; }
    if (tid < 64) wab[tid] = act_b[tid];
    for (int i = tid; i < 4096; i += 256) { int c=i>>6, o=i&63; wWEt[i] = edge_g[o]*edge_W[o*128+c]; }
    __syncthreads();

    float4 mx[8];
    #pragma unroll
    for (int oo = 0; oo < 8; oo++) mx[oo] = make_float4(-1e30f,-1e30f,-1e30f,-1e30f);

    #pragma unroll 1
    for (int k = 0; k < NK; k++) {
        // ---- stage input tiles (coalesced) ----
        {
            const float* src = g_apT + (((size_t)b*NK + k)*8)*NN + n0;
            int f = tid*4;                       // 1024 floats
            int c = f >> 7, col = f & 127;
            *(float4*)&t_in[f] = *(const float4*)&src[c*NN + col];
        }
        {
            const float* src = g_glT + (((size_t)b*NK + k)*32)*NN + n0;
            #pragma unroll
            for (int u = 0; u < 4; u++) {
                int f = (tid + u*256)*4;         // 4096 floats
                int c = f >> 7, col = f & 127;
                *(float4*)&t_rif[(32+c)*128 + col] = *(const float4*)&src[c*NN + col];
            }
        }
        if (tid < 128) s_idx[tid] = g_idxT[((size_t)b*NK + k)*NN + n0 + tid];
        __syncthreads();

        // ---- GEMM1: dk1 [16x128], K=8, thread 2o x 4p ----
        {
            const int o0 = w*2;
            float4 a0 = make_float4(0,0,0,0), a1 = a0;
            #pragma unroll
            for (int c = 0; c < 8; c++) {
                float w0 = wW1t[c*16 + o0], w1 = wW1t[c*16 + o0 + 1];
                float4 bv = *(float4*)&t_in[c*128 + p0];
                a0.x += w0*bv.x; a0.y += w0*bv.y; a0.z += w0*bv.z; a0.w += w0*bv.w;
                a1.x += w1*bv.x; a1.y += w1*bv.y; a1.z += w1*bv.z; a1.w += w1*bv.w;
            }
            float b0 = wb1[o0], b1v = wb1[o0+1];
            a0.x = fmaxf(a0.x+b0,0.f); a0.y = fmaxf(a0.y+b0,0.f); a0.z = fmaxf(a0.z+b0,0.f); a0.w = fmaxf(a0.w+b0,0.f);
            a1.x = fmaxf(a1.x+b1v,0.f); a1.y = fmaxf(a1.y+b1v,0.f); a1.z = fmaxf(a1.z+b1v,0.f); a1.w = fmaxf(a1.w+b1v,0.f);
            *(float4*)&t_h[o0*128 + p0] = a0;
            *(float4*)&t_h[(o0+1)*128 + p0] = a1;
        }
        __syncthreads();

        // ---- GEMM2: dk2 [32x128], K=16, thread 4o x 4p -> rif rows 0..31 ----
        {
            const int o0 = w*4;
            float4 acc[4];
            #pragma unroll
            for (int oo = 0; oo < 4; oo++) acc[oo] = make_float4(0,0,0,0);
            #pragma unroll
            for (int c = 0; c < 16; c++) {
                float4 wa = *(float4*)&wW2t[c*32 + o0];
                float4 bv = *(float4*)&t_h[c*128 + p0];
                acc[0].x += wa.x*bv.x; acc[0].y += wa.x*bv.y; acc[0].z += wa.x*bv.z; acc[0].w += wa.x*bv.w;
                acc[1].x += wa.y*bv.x; acc[1].y += wa.y*bv.y; acc[1].z += wa.y*bv.z; acc[1].w += wa.y*bv.w;
                acc[2].x += wa.z*bv.x; acc[2].y += wa.z*bv.y; acc[2].z += wa.z*bv.z; acc[2].w += wa.z*bv.w;
                acc[3].x += wa.w*bv.x; acc[3].y += wa.w*bv.y; acc[3].z += wa.w*bv.z; acc[3].w += wa.w*bv.w;
            }
            #pragma unroll
            for (int oo = 0; oo < 4; oo++) {
                float bb = wb2[o0+oo];
                acc[oo].x += bb; acc[oo].y += bb; acc[oo].z += bb; acc[oo].w += bb;
                *(float4*)&t_rif[(o0+oo)*128 + p0] = acc[oo];
            }
        }
        __syncthreads();

        // ---- GEMM3: ff1 [32x128], K=64, thread 4o x 4p, leaky(bn) ----
        {
            const int o0 = w*4;
            float4 acc[4];
            #pragma unroll
            for (int oo = 0; oo < 4; oo++) acc[oo] = make_float4(0,0,0,0);
            #pragma unroll 8
            for (int c = 0; c < 64; c++) {
                float4 wa = *(float4*)&wF1t[c*32 + o0];
                float4 bv = *(float4*)&t_rif[c*128 + p0];
                acc[0].x += wa.x*bv.x; acc[0].y += wa.x*bv.y; acc[0].z += wa.x*bv.z; acc[0].w += wa.x*bv.w;
                acc[1].x += wa.y*bv.x; acc[1].y += wa.y*bv.y; acc[1].z += wa.y*bv.z; acc[1].w += wa.y*bv.w;
                acc[2].x += wa.z*bv.x; acc[2].y += wa.z*bv.y; acc[2].z += wa.z*bv.z; acc[2].w += wa.z*bv.w;
                acc[3].x += wa.w*bv.x; acc[3].y += wa.w*bv.y; acc[3].z += wa.w*bv.z; acc[3].w += wa.w*bv.w;
            }
            #pragma unroll
            for (int oo = 0; oo < 4; oo++) {
                float bb = wbf[o0+oo];
                float4 v = acc[oo];
                v.x = LEAKY(v.x+bb); v.y = LEAKY(v.y+bb); v.z = LEAKY(v.z+bb); v.w = LEAKY(v.w+bb);
                *(float4*)&t_att[(o0+oo)*128 + p0] = v;
            }
        }
        __syncthreads();

        // ---- GEMM4: ff2 [64x128], K=32, thread 8o x 4p; sigmoid; gate in place ----
        {
            const int o0 = w*8;
            float4 acc[8];
            #pragma unroll
            for (int oo = 0; oo < 8; oo++) acc[oo] = make_float4(0,0,0,0);
            #pragma unroll 8
            for (int c = 0; c < 32; c++) {
                float4 wa0 = *(float4*)&wF2t[c*64 + o0];
                float4 wa1 = *(float4*)&wF2t[c*64 + o0 + 4];
                float4 bv  = *(float4*)&t_att[c*128 + p0];
                acc[0].x += wa0.x*bv.x; acc[0].y += wa0.x*bv.y; acc[0].z += wa0.x*bv.z; acc[0].w += wa0.x*bv.w;
                acc[1].x += wa0.y*bv.x; acc[1].y += wa0.y*bv.y; acc[1].z += wa0.y*bv.z; acc[1].w += wa0.y*bv.w;
                acc[2].x += wa0.z*bv.x; acc[2].y += wa0.z*bv.y; acc[2].z += wa0.z*bv.z; acc[2].w += wa0.z*bv.w;
                acc[3].x += wa0.w*bv.x; acc[3].y += wa0.w*bv.y; acc[3].z += wa0.w*bv.z; acc[3].w += wa0.w*bv.w;
                acc[4].x += wa1.x*bv.x; acc[4].y += wa1.x*bv.y; acc[4].z += wa1.x*bv.z; acc[4].w += wa1.x*bv.w;
                acc[5].x += wa1.y*bv.x; acc[5].y += wa1.y*bv.y; acc[5].z += wa1.y*bv.z; acc[5].w += wa1.y*bv.w;
                acc[6].x += wa1.z*bv.x; acc[6].y += wa1.z*bv.y; acc[6].z += wa1.z*bv.z; acc[6].w += wa1.z*bv.w;
                acc[7].x += wa1.w*bv.x; acc[7].y += wa1.w*bv.y; acc[7].z += wa1.w*bv.z; acc[7].w += wa1.w*bv.w;
            }
            #pragma unroll
            for (int oo = 0; oo < 8; oo++) {
                acc[oo].x = 1.f/(1.f + __expf(-acc[oo].x));
                acc[oo].y = 1.f/(1.f + __expf(-acc[oo].y));
                acc[oo].z = 1.f/(1.f + __expf(-acc[oo].z));
                acc[oo].w = 1.f/(1.f + __expf(-acc[oo].w));
            }
            // gate: feat = relu(rif * sig * bx_gather + act_b), in place in t_rif
            #pragma unroll
            for (int pp = 0; pp < 4; pp++) {
                int j = s_idx[p0 + pp];
                const float4* bxp = (const float4*)(g_bxT + ((size_t)b*NN + j)*64 + o0);
                float4 bx0 = bxp[0], bx1 = bxp[1];
                float bxv[8] = {bx0.x,bx0.y,bx0.z,bx0.w,bx1.x,bx1.y,bx1.z,bx1.w};
                #pragma unroll
                for (int oo = 0; oo < 8; oo++) {
                    float sg = (pp==0) ? acc[oo].x : (pp==1) ? acc[oo].y : (pp==2) ? acc[oo].z : acc[oo].w;
                    int a = (o0+oo)*128 + p0 + pp;
                    float rv = t_rif[a];
                    t_rif[a] = fmaxf(rv*sg*bxv[oo] + wab[o0+oo], 0.f);
                }
            }
        }
        __syncthreads();

        // ---- GEMM5: edge [64x128], K=64, thread 8o x 4p; running max (leaky+cst deferred) ----
        {
            const int o0 = w*8;
            float4 acc[8];
            #pragma unroll
            for (int oo = 0; oo < 8; oo++) acc[oo] = make_float4(0,0,0,0);
            #pragma unroll 8
            for (int c = 0; c < 64; c++) {
                float4 wa0 = *(float4*)&wWEt[c*64 + o0];
                float4 wa1 = *(float4*)&wWEt[c*64 + o0 + 4];
                float4 bv  = *(float4*)&t_rif[c*128 + p0];
                acc[0].x += wa0.x*bv.x; acc[0].y += wa0.x*bv.y; acc[0].z += wa0.x*bv.z; acc[0].w += wa0.x*bv.w;
                acc[1].x += wa0.y*bv.x; acc[1].y += wa0.y*bv.y; acc[1].z += wa0.y*bv.z; acc[1].w += wa0.y*bv.w;
                acc[2].x += wa0.z*bv.x; acc[2].y += wa0.z*bv.y; acc[2].z += wa0.z*bv.z; acc[2].w += wa0.z*bv.w;
                acc[3].x += wa0.w*bv.x; acc[3].y += wa0.w*bv.y; acc[3].z += wa0.w*bv.z; acc[3].w += wa0.w*bv.w;
                acc[4].x += wa1.x*bv.x; acc[4].y += wa1.x*bv.y; acc[4].z += wa1.x*bv.z; acc[4].w += wa1.x*bv.w;
                acc[5].x += wa1.y*bv.x; acc[5].y += wa1.y*bv.y; acc[5].z += wa1.y*bv.z; acc[5].w += wa1.y*bv.w;
                acc[6].x += wa1.z*bv.x; acc[6].y += wa1.z*bv.y; acc[6].z += wa1.z*bv.z; acc[6].w += wa1.z*bv.w;
                acc[7].x += wa1.w*bv.x; acc[7].y += wa1.w*bv.y; acc[7].z += wa1.w*bv.z; acc[7].w += wa1.w*bv.w;
            }
            #pragma unroll
            for (int oo = 0; oo < 8; oo++) {
                mx[oo].x = fmaxf(mx[oo].x, acc[oo].x);
                mx[oo].y = fmaxf(mx[oo].y, acc[oo].y);
                mx[oo].z = fmaxf(mx[oo].z, acc[oo].z);
                mx[oo].w = fmaxf(mx[oo].w, acc[oo].w);
            }
        }
        __syncthreads();
    }

    // ---- epilogue: out = leaky(mx + cst), write coalesced along n ----
    {
        const int o0 = w*8;
        float4 c0[4], c1[4];
        #pragma unroll
        for (int pp = 0; pp < 4; pp++) {
            const float4* cp = (const float4*)(g_cst + ((size_t)b*NN + n0 + p0 + pp)*64 + o0);
            c0[pp] = cp[0]; c1[pp] = cp[1];
        }
        #pragma unroll
        for (int oo = 0; oo < 8; oo++) {
            float cc[4];
            #pragma unroll
            for (int pp = 0; pp < 4; pp++) {
                float4 cv = (oo < 4) ? c0[pp] : c1[pp];
                int q = oo & 3;
                cc[pp] = (q==0) ? cv.x : (q==1) ? cv.y : (q==2) ? cv.z : cv.w;
            }
            float4 v;
            v.x = LEAKY(mx[oo].x + cc[0]);
            v.y = LEAKY(mx[oo].y + cc[1]);
            v.z = LEAKY(mx[oo].z + cc[2]);
            v.w = LEAKY(mx[oo].w + cc[3]);
            *(float4*)&out[((size_t)b*64 + o0 + oo)*NN + n0 + p0] = v;
        }
    }
}

// =====================================================================
extern "C" void kernel_launch(void* const* d_in, const int* in_sizes, int n_in,
                              void* d_out, int out_size)
{
    const float* pos     = (const float*)d_in[0];
    const float* x       = (const float*)d_in[1];
    const float* glf     = (const float*)d_in[2];
    const float* appf    = (const float*)d_in[3];
    const float* basis_W = (const float*)d_in[4];
    const float* dk_W1   = (const float*)d_in[5];
    const float* dk_b1   = (const float*)d_in[6];
    const float* dk_g1   = (const float*)d_in[7];
    const float* dk_be1  = (const float*)d_in[8];
    const float* dk_W2   = (const float*)d_in[9];
    const float* dk_b2   = (const float*)d_in[10];
    const float* act_g   = (const float*)d_in[11];
    const float* act_b   = (const float*)d_in[12];
    const float* ff_W1   = (const float*)d_in[13];
    const float* ff_g1   = (const float*)d_in[14];
    const float* ff_be1  = (const float*)d_in[15];
    const float* ff_W2   = (const float*)d_in[16];
    const float* edge_W  = (const float*)d_in[17];
    const float* edge_g  = (const float*)d_in[18];
    const float* edge_be = (const float*)d_in[19];
    float* out = (float*)d_out;

    knn_kernel<<<dim3(NN/256, NB), 256>>>(pos);
    prep_kernel<<<(NB*NN)/128, 128>>>(x, basis_W, edge_W, act_g, edge_g, edge_be);
    ap_tr_kernel<<<dim3(NN/32, NB), 256>>>(appf);
    glf_tr_kernel<<<dim3(NN/64, 32, NB), 256>>>(glf);

    const int smem_bytes = (128+16+512+32+2048+32+2048+64+4096 + 1024+2048+8192+4096 + 128) * (int)sizeof(float);
    cudaFuncSetAttribute(main_kernel, cudaFuncAttributeMaxDynamicSharedMemorySize, smem_bytes);
    main_kernel<<<NB*NN/128, 256, smem_bytes>>>(dk_W1, dk_b1, dk_g1, dk_be1,
                                                dk_W2, dk_b2, act_b,
                                                ff_W1, ff_g1, ff_be1, ff_W2,
                                                edge_W, edge_g, out);
}

// round 4
// speedup vs baseline: 1.8787x; 1.0469x over previous
#include <cuda_runtime.h>
#include <math.h>

#define NB 16
#define NN 2048
#define NK 20
#define NC 64

typedef unsigned long long u64;

// ---- scratch (static __device__, allocation-free) ----
__device__ int   g_idxT[NB*NK*NN];          // knn indices, [b][k][n]
__device__ float g_bxT [NB*NN*NC];          // act_g * (basis_W @ x), point-major [p][c]
__device__ float g_cst [NB*NN*NC];          // edge_g*((We2-We1)@x) + edge_be, [p][o]
__device__ float g_apT [NB*NK*8*NN];        // appf transposed to [b][k][c][n]
__device__ float g_glT [NB*NK*32*NN];       // glf  transposed to [b][k][c][n]

// ---- packed f32x2 helpers (Blackwell FFMA2) ----
__device__ __forceinline__ u64 f2pack(float lo, float hi) {
    u64 r; asm("mov.b64 %0, {%1, %2};" : "=l"(r) : "f"(lo), "f"(hi)); return r;
}
__device__ __forceinline__ void f2unpack(u64 v, float& lo, float& hi) {
    asm("mov.b64 {%0, %1}, %2;" : "=f"(lo), "=f"(hi) : "l"(v));
}
__device__ __forceinline__ void ffma2(u64& d, u64 a, u64 b) {
    asm("fma.rn.f32x2 %0, %1, %2, %3;" : "=l"(d) : "l"(a), "l"(b), "l"(d));
}

// =====================================================================
// KNN: per (b,q) top-20 by pd = 2<pq,pm> - |pq|^2 - |pm|^2 (excl self)
// =====================================================================
__global__ void knn_kernel(const float* __restrict__ pos)
{
    __shared__ float4 sp[NN];
    const int b   = blockIdx.y;
    const int tid = threadIdx.x;
    const float* pb = pos + (size_t)b*3*NN;
    for (int m = tid; m < NN; m += blockDim.x) {
        float x = pb[m], y = pb[NN + m], z = pb[2*NN + m];
        sp[m] = make_float4(x, y, z, x*x + y*y + z*z);
    }
    __syncthreads();
    const int q = blockIdx.x * blockDim.x + tid;
    const float4 pq = sp[q];

    float tv[NK]; int ti[NK];
    #pragma unroll
    for (int i = 0; i < NK; i++) { tv[i] = -1e30f; ti[i] = 0; }

    #pragma unroll 1
    for (int m = 0; m < NN; m++) {
        if (m == q) continue;
        float4 pm = sp[m];
        float pd = 2.0f*(pq.x*pm.x + pq.y*pm.y + pq.z*pm.z) - pq.w - pm.w;
        if (pd > tv[NK-1]) {
            tv[NK-1] = pd; ti[NK-1] = m;
            #pragma unroll
            for (int i = NK-1; i > 0; i--) {
                if (tv[i] > tv[i-1]) {       // strict: ties keep lower index first
                    float fv = tv[i-1]; tv[i-1] = tv[i]; tv[i] = fv;
                    int   iv = ti[i-1]; ti[i-1] = ti[i]; ti[i] = iv;
                }
            }
        }
    }
    #pragma unroll
    for (int i = 0; i < NK; i++)
        g_idxT[((size_t)b*NK + i)*NN + q] = ti[i];
}

// =====================================================================
// prep: g_bxT[p][c] = act_g[c] * (basis_W @ x)[c]
//       g_cst[p][o] = edge_g[o] * ((We2-We1)@x)[o] + edge_be[o]
// =====================================================================
__global__ void prep_kernel(const float* __restrict__ x,
                            const float* __restrict__ basis_W,
                            const float* __restrict__ edge_W,
                            const float* __restrict__ act_g,
                            const float* __restrict__ edge_g,
                            const float* __restrict__ edge_be)
{
    __shared__ float sB[64*64];
    __shared__ float sD[64*64];
    __shared__ float sag[64], seg[64], seb[64];
    const int tid = threadIdx.x;
    for (int i = tid; i < 4096; i += blockDim.x) {
        sB[i] = basis_W[i];
        int o = i >> 6, c = i & 63;
        sD[i] = edge_W[o*128 + 64 + c] - edge_W[o*128 + c];
    }
    for (int i = tid; i < 64; i += blockDim.x) {
        sag[i] = act_g[i]; seg[i] = edge_g[i]; seb[i] = edge_be[i];
    }
    __syncthreads();

    const int p = blockIdx.x * blockDim.x + tid;
    const int b = p / NN, n = p % NN;
    const float* xp = x + (size_t)b*64*NN + n;
    float xv[64];
    #pragma unroll
    for (int c = 0; c < 64; c++) xv[c] = xp[(size_t)c*NN];

    float* bo = g_bxT + (size_t)p*64;
    #pragma unroll 4
    for (int o = 0; o < 64; o++) {
        float acc = 0.f;
        #pragma unroll
        for (int c = 0; c < 64; c++) acc += sB[o*64+c]*xv[c];
        bo[o] = acc * sag[o];
    }
    float* co = g_cst + (size_t)p*64;
    #pragma unroll 4
    for (int o = 0; o < 64; o++) {
        float acc = 0.f;
        #pragma unroll
        for (int c = 0; c < 64; c++) acc += sD[o*64+c]*xv[c];
        co[o] = acc*seg[o] + seb[o];
    }
}

// =====================================================================
// appf transpose: (B,N,K,8) -> [b][k][c][n]
// =====================================================================
__global__ void ap_tr_kernel(const float* __restrict__ appf)
{
    __shared__ float s[32*161];
    const int b  = blockIdx.y;
    const int n0 = blockIdx.x * 32;
    const int tid = threadIdx.x;
    const float* in = appf + ((size_t)b*NN + n0) * (NK*8);
    #pragma unroll
    for (int u = 0; u < 20; u++) {
        int f = tid + u*256;
        int n = f / 160, r = f % 160;
        s[n*161 + r] = in[f];
    }
    __syncthreads();
    #pragma unroll
    for (int u = 0; u < 20; u++) {
        int f = tid + u*256;
        int row = f >> 5, n = f & 31;
        g_apT[((size_t)b*NK*8 + row)*NN + n0 + n] = s[n*161 + row];
    }
}

// =====================================================================
// glf transpose: (B,32,N,K) -> [b][k][c][n]
// =====================================================================
__global__ void glf_tr_kernel(const float* __restrict__ glf)
{
    __shared__ float s[64*21];
    const int n0 = blockIdx.x * 64;
    const int c  = blockIdx.y;
    const int b  = blockIdx.z;
    const int tid = threadIdx.x;
    const float* in = glf + (((size_t)b*32 + c)*NN + n0) * NK;
    #pragma unroll
    for (int u = 0; u < 5; u++) {
        int f = tid + u*256;
        int n = f / 20, k = f % 20;
        s[n*21 + k] = in[f];
    }
    __syncthreads();
    #pragma unroll
    for (int u = 0; u < 5; u++) {
        int f = tid + u*256;
        int k = f >> 6, n = f & 63;
        g_glT[(((size_t)b*NK + k)*32 + c)*NN + n0 + n] = s[n*21 + k];
    }
}

// =====================================================================
// main fused kernel: CTA = 256 threads, 128-point tile, k-loop inside.
// GEMM inner loops use packed fma.rn.f32x2 (o-pair accumulators).
// =====================================================================
#define LEAKY(v) ((v) > 0.f ? (v) : 0.2f*(v))

__global__ void __launch_bounds__(256, 2)
main_kernel(const float* __restrict__ dk_W1, const float* __restrict__ dk_b1,
            const float* __restrict__ dk_g1, const float* __restrict__ dk_be1,
            const float* __restrict__ dk_W2, const float* __restrict__ dk_b2,
            const float* __restrict__ act_b,
            const float* __restrict__ ff_W1, const float* __restrict__ ff_g1,
            const float* __restrict__ ff_be1, const float* __restrict__ ff_W2,
            const float* __restrict__ edge_W, const float* __restrict__ edge_g,
            float* __restrict__ out)
{
    extern __shared__ float sm[];
    float* wW1t = sm;             // [8][16]   128
    float* wb1  = wW1t + 128;     // 16
    float* wW2t = wb1  + 16;      // [16][32]  512
    float* wb2  = wW2t + 512;     // 32
    float* wF1t = wb2  + 32;      // [64][32]  2048
    float* wbf  = wF1t + 2048;    // 32
    float* wF2t = wbf  + 32;      // [32][64]  2048
    float* wab  = wF2t + 2048;    // 64
    float* wWEt = wab  + 64;      // [64][64]  4096
    float* t_in = wWEt + 4096;    // [8][128]  1024
    float* t_h  = t_in + 1024;    // [16][128] 2048
    float* t_rif= t_h  + 2048;    // [64][128] 8192 (becomes feat in place)
    float* t_att= t_rif+ 8192;    // [32][128] 4096
    int*   s_idx= (int*)(t_att + 4096);   // 128

    const int tid = threadIdx.x;
    const int w   = tid >> 5;
    const int l   = tid & 31;
    const int p0  = l*4;
    const int b   = blockIdx.x >> 4;
    const int n0  = (blockIdx.x & 15) << 7;

    // ---- stage folded, transposed weights ----
    for (int i = tid; i < 128; i += 256) { int c=i>>4, o=i&15; wW1t[i] = dk_g1[o]*dk_W1[o*8+c]; }
    if (tid < 16) wb1[tid] = dk_g1[tid]*dk_b1[tid] + dk_be1[tid];
    for (int i = tid; i < 512; i += 256) { int c=i>>5, o=i&31; wW2t[i] = dk_W2[o*16+c]; }
    if (tid < 32) wb2[tid] = dk_b2[tid];
    for (int i = tid; i < 2048; i += 256) { int c=i>>5, o=i&31; wF1t[i] = ff_g1[o]*ff_W1[o*64+c]; }
    if (tid < 32) wbf[tid] = ff_be1[tid];
    for (int i = tid; i < 2048; i += 256) { int c=i>>6, o=i&63; wF2t[i] = ff_W2[o*32+c]; }
    if (tid < 64) wab[tid] = act_b[tid];
    for (int i = tid; i < 4096; i += 256) { int c=i>>6, o=i&63; wWEt[i] = edge_g[o]*edge_W[o*128+c]; }
    __syncthreads();

    float mx[4][8];                         // [point][o]
    #pragma unroll
    for (int pp = 0; pp < 4; pp++)
        #pragma unroll
        for (int oo = 0; oo < 8; oo++) mx[pp][oo] = -1e30f;

    #pragma unroll 1
    for (int k = 0; k < NK; k++) {
        // ---- stage input tiles (coalesced) ----
        {
            const float* src = g_apT + (((size_t)b*NK + k)*8)*NN + n0;
            int f = tid*4;
            int c = f >> 7, col = f & 127;
            *(float4*)&t_in[f] = *(const float4*)&src[c*NN + col];
        }
        {
            const float* src = g_glT + (((size_t)b*NK + k)*32)*NN + n0;
            #pragma unroll
            for (int u = 0; u < 4; u++) {
                int f = (tid + u*256)*4;
                int c = f >> 7, col = f & 127;
                *(float4*)&t_rif[(32+c)*128 + col] = *(const float4*)&src[c*NN + col];
            }
        }
        if (tid < 128) s_idx[tid] = g_idxT[((size_t)b*NK + k)*NN + n0 + tid];
        __syncthreads();

        // ---- GEMM1: dk1 [16x128], K=8, warp owns o-pair (2o) x 128p ----
        {
            const int o0 = w*2;
            const u64 bias = *(const u64*)&wb1[o0];
            u64 a0 = bias, a1 = bias, a2 = bias, a3 = bias;
            #pragma unroll
            for (int c = 0; c < 8; c++) {
                u64 wv = *(const u64*)&wW1t[c*16 + o0];
                float4 bv = *(float4*)&t_in[c*128 + p0];
                ffma2(a0, wv, f2pack(bv.x, bv.x));
                ffma2(a1, wv, f2pack(bv.y, bv.y));
                ffma2(a2, wv, f2pack(bv.z, bv.z));
                ffma2(a3, wv, f2pack(bv.w, bv.w));
            }
            float l0,h0,l1,h1,l2,h2,l3,h3;
            f2unpack(a0,l0,h0); f2unpack(a1,l1,h1); f2unpack(a2,l2,h2); f2unpack(a3,l3,h3);
            float4 r0 = make_float4(fmaxf(l0,0.f), fmaxf(l1,0.f), fmaxf(l2,0.f), fmaxf(l3,0.f));
            float4 r1 = make_float4(fmaxf(h0,0.f), fmaxf(h1,0.f), fmaxf(h2,0.f), fmaxf(h3,0.f));
            *(float4*)&t_h[o0*128 + p0] = r0;
            *(float4*)&t_h[(o0+1)*128 + p0] = r1;
        }
        __syncthreads();

        // ---- GEMM2: dk2 [32x128], K=16, 4o x 4p, bias only ----
        {
            const int o0 = w*4;
            ulonglong2 bi = *(const ulonglong2*)&wb2[o0];
            u64 acc[4][2];
            #pragma unroll
            for (int pp = 0; pp < 4; pp++) { acc[pp][0] = bi.x; acc[pp][1] = bi.y; }
            #pragma unroll
            for (int c = 0; c < 16; c++) {
                ulonglong2 wv = *(const ulonglong2*)&wW2t[c*32 + o0];
                float4 bv = *(float4*)&t_h[c*128 + p0];
                u64 bx = f2pack(bv.x,bv.x), by = f2pack(bv.y,bv.y);
                u64 bz = f2pack(bv.z,bv.z), bw = f2pack(bv.w,bv.w);
                ffma2(acc[0][0], wv.x, bx); ffma2(acc[0][1], wv.y, bx);
                ffma2(acc[1][0], wv.x, by); ffma2(acc[1][1], wv.y, by);
                ffma2(acc[2][0], wv.x, bz); ffma2(acc[2][1], wv.y, bz);
                ffma2(acc[3][0], wv.x, bw); ffma2(acc[3][1], wv.y, bw);
            }
            #pragma unroll
            for (int pr = 0; pr < 2; pr++) {
                float l0,h0,l1,h1,l2,h2,l3,h3;
                f2unpack(acc[0][pr],l0,h0); f2unpack(acc[1][pr],l1,h1);
                f2unpack(acc[2][pr],l2,h2); f2unpack(acc[3][pr],l3,h3);
                *(float4*)&t_rif[(o0+2*pr)*128 + p0]   = make_float4(l0,l1,l2,l3);
                *(float4*)&t_rif[(o0+2*pr+1)*128 + p0] = make_float4(h0,h1,h2,h3);
            }
        }
        __syncthreads();

        // ---- GEMM3: ff1 [32x128], K=64, 4o x 4p, leaky(bn) ----
        {
            const int o0 = w*4;
            ulonglong2 bi = *(const ulonglong2*)&wbf[o0];
            u64 acc[4][2];
            #pragma unroll
            for (int pp = 0; pp < 4; pp++) { acc[pp][0] = bi.x; acc[pp][1] = bi.y; }
            #pragma unroll 4
            for (int c = 0; c < 64; c++) {
                ulonglong2 wv = *(const ulonglong2*)&wF1t[c*32 + o0];
                float4 bv = *(float4*)&t_rif[c*128 + p0];
                u64 bx = f2pack(bv.x,bv.x), by = f2pack(bv.y,bv.y);
                u64 bz = f2pack(bv.z,bv.z), bw = f2pack(bv.w,bv.w);
                ffma2(acc[0][0], wv.x, bx); ffma2(acc[0][1], wv.y, bx);
                ffma2(acc[1][0], wv.x, by); ffma2(acc[1][1], wv.y, by);
                ffma2(acc[2][0], wv.x, bz); ffma2(acc[2][1], wv.y, bz);
                ffma2(acc[3][0], wv.x, bw); ffma2(acc[3][1], wv.y, bw);
            }
            #pragma unroll
            for (int pr = 0; pr < 2; pr++) {
                float l0,h0,l1,h1,l2,h2,l3,h3;
                f2unpack(acc[0][pr],l0,h0); f2unpack(acc[1][pr],l1,h1);
                f2unpack(acc[2][pr],l2,h2); f2unpack(acc[3][pr],l3,h3);
                *(float4*)&t_att[(o0+2*pr)*128 + p0] =
                    make_float4(LEAKY(l0),LEAKY(l1),LEAKY(l2),LEAKY(l3));
                *(float4*)&t_att[(o0+2*pr+1)*128 + p0] =
                    make_float4(LEAKY(h0),LEAKY(h1),LEAKY(h2),LEAKY(h3));
            }
        }
        __syncthreads();

        // ---- GEMM4: ff2 [64x128], K=32, 8o x 4p; sigmoid; gate in place ----
        {
            const int o0 = w*8;
            u64 acc[4][4];
            #pragma unroll
            for (int pp = 0; pp < 4; pp++)
                #pragma unroll
                for (int pr = 0; pr < 4; pr++) acc[pp][pr] = 0ull;
            #pragma unroll 4
            for (int c = 0; c < 32; c++) {
                ulonglong2 wA = *(const ulonglong2*)&wF2t[c*64 + o0];
                ulonglong2 wB = *(const ulonglong2*)&wF2t[c*64 + o0 + 4];
                float4 bv = *(float4*)&t_att[c*128 + p0];
                u64 bx = f2pack(bv.x,bv.x), by = f2pack(bv.y,bv.y);
                u64 bz = f2pack(bv.z,bv.z), bw = f2pack(bv.w,bv.w);
                ffma2(acc[0][0], wA.x, bx); ffma2(acc[0][1], wA.y, bx);
                ffma2(acc[0][2], wB.x, bx); ffma2(acc[0][3], wB.y, bx);
                ffma2(acc[1][0], wA.x, by); ffma2(acc[1][1], wA.y, by);
                ffma2(acc[1][2], wB.x, by); ffma2(acc[1][3], wB.y, by);
                ffma2(acc[2][0], wA.x, bz); ffma2(acc[2][1], wA.y, bz);
                ffma2(acc[2][2], wB.x, bz); ffma2(acc[2][3], wB.y, bz);
                ffma2(acc[3][0], wA.x, bw); ffma2(acc[3][1], wA.y, bw);
                ffma2(acc[3][2], wB.x, bw); ffma2(acc[3][3], wB.y, bw);
            }
            // gate in two o-halves to bound register pressure
            #pragma unroll
            for (int hh = 0; hh < 2; hh++) {
                float sg[4][4];      // [point][o within half]
                float bxv[4][4];
                #pragma unroll
                for (int pp = 0; pp < 4; pp++) {
                    float lo, hi;
                    f2unpack(acc[pp][2*hh],   lo, hi);
                    sg[pp][0] = 1.f/(1.f + __expf(-lo));
                    sg[pp][1] = 1.f/(1.f + __expf(-hi));
                    f2unpack(acc[pp][2*hh+1], lo, hi);
                    sg[pp][2] = 1.f/(1.f + __expf(-lo));
                    sg[pp][3] = 1.f/(1.f + __expf(-hi));
                    int j = s_idx[p0 + pp];
                    float4 gv = *(const float4*)(g_bxT + ((size_t)b*NN + j)*64 + o0 + 4*hh);
                    bxv[pp][0] = gv.x; bxv[pp][1] = gv.y; bxv[pp][2] = gv.z; bxv[pp][3] = gv.w;
                }
                #pragma unroll
                for (int oo = 0; oo < 4; oo++) {
                    int row = o0 + 4*hh + oo;
                    float ab = wab[row];
                    float4 rv = *(float4*)&t_rif[row*128 + p0];
                    rv.x = fmaxf(rv.x * sg[0][oo] * bxv[0][oo] + ab, 0.f);
                    rv.y = fmaxf(rv.y * sg[1][oo] * bxv[1][oo] + ab, 0.f);
                    rv.z = fmaxf(rv.z * sg[2][oo] * bxv[2][oo] + ab, 0.f);
                    rv.w = fmaxf(rv.w * sg[3][oo] * bxv[3][oo] + ab, 0.f);
                    *(float4*)&t_rif[row*128 + p0] = rv;
                }
            }
        }
        __syncthreads();

        // ---- GEMM5: edge [64x128], K=64, 8o x 4p; running max (leaky+cst deferred) ----
        {
            const int o0 = w*8;
            u64 acc[4][4];
            #pragma unroll
            for (int pp = 0; pp < 4; pp++)
                #pragma unroll
                for (int pr = 0; pr < 4; pr++) acc[pp][pr] = 0ull;
            #pragma unroll 4
            for (int c = 0; c < 64; c++) {
                ulonglong2 wA = *(const ulonglong2*)&wWEt[c*64 + o0];
                ulonglong2 wB = *(const ulonglong2*)&wWEt[c*64 + o0 + 4];
                float4 bv = *(float4*)&t_rif[c*128 + p0];
                u64 bx = f2pack(bv.x,bv.x), by = f2pack(bv.y,bv.y);
                u64 bz = f2pack(bv.z,bv.z), bw = f2pack(bv.w,bv.w);
                ffma2(acc[0][0], wA.x, bx); ffma2(acc[0][1], wA.y, bx);
                ffma2(acc[0][2], wB.x, bx); ffma2(acc[0][3], wB.y, bx);
                ffma2(acc[1][0], wA.x, by); ffma2(acc[1][1], wA.y, by);
                ffma2(acc[1][2], wB.x, by); ffma2(acc[1][3], wB.y, by);
                ffma2(acc[2][0], wA.x, bz); ffma2(acc[2][1], wA.y, bz);
                ffma2(acc[2][2], wB.x, bz); ffma2(acc[2][3], wB.y, bz);
                ffma2(acc[3][0], wA.x, bw); ffma2(acc[3][1], wA.y, bw);
                ffma2(acc[3][2], wB.x, bw); ffma2(acc[3][3], wB.y, bw);
            }
            #pragma unroll
            for (int pp = 0; pp < 4; pp++) {
                #pragma unroll
                for (int pr = 0; pr < 4; pr++) {
                    float lo, hi;
                    f2unpack(acc[pp][pr], lo, hi);
                    mx[pp][2*pr]   = fmaxf(mx[pp][2*pr],   lo);
                    mx[pp][2*pr+1] = fmaxf(mx[pp][2*pr+1], hi);
                }
            }
        }
        __syncthreads();
    }

    // ---- epilogue: out = leaky(mx + cst), write coalesced along n ----
    {
        const int o0 = w*8;
        #pragma unroll
        for (int hh = 0; hh < 2; hh++) {
            float cc[4][4];
            #pragma unroll
            for (int pp = 0; pp < 4; pp++) {
                float4 cv = *(const float4*)(g_cst + ((size_t)b*NN + n0 + p0 + pp)*64 + o0 + 4*hh);
                cc[pp][0]=cv.x; cc[pp][1]=cv.y; cc[pp][2]=cv.z; cc[pp][3]=cv.w;
            }
            #pragma unroll
            for (int oo = 0; oo < 4; oo++) {
                int row = o0 + 4*hh + oo;
                float4 v;
                v.x = LEAKY(mx[0][4*hh+oo] + cc[0][oo]);
                v.y = LEAKY(mx[1][4*hh+oo] + cc[1][oo]);
                v.z = LEAKY(mx[2][4*hh+oo] + cc[2][oo]);
                v.w = LEAKY(mx[3][4*hh+oo] + cc[3][oo]);
                *(float4*)&out[((size_t)b*64 + row)*NN + n0 + p0] = v;
            }
        }
    }
}

// =====================================================================
extern "C" void kernel_launch(void* const* d_in, const int* in_sizes, int n_in,
                              void* d_out, int out_size)
{
    const float* pos     = (const float*)d_in[0];
    const float* x       = (const float*)d_in[1];
    const float* glf     = (const float*)d_in[2];
    const float* appf    = (const float*)d_in[3];
    const float* basis_W = (const float*)d_in[4];
    const float* dk_W1   = (const float*)d_in[5];
    const float* dk_b1   = (const float*)d_in[6];
    const float* dk_g1   = (const float*)d_in[7];
    const float* dk_be1  = (const float*)d_in[8];
    const float* dk_W2   = (const float*)d_in[9];
    const float* dk_b2   = (const float*)d_in[10];
    const float* act_g   = (const float*)d_in[11];
    const float* act_b   = (const float*)d_in[12];
    const float* ff_W1   = (const float*)d_in[13];
    const float* ff_g1   = (const float*)d_in[14];
    const float* ff_be1  = (const float*)d_in[15];
    const float* ff_W2   = (const float*)d_in[16];
    const float* edge_W  = (const float*)d_in[17];
    const float* edge_g  = (const float*)d_in[18];
    const float* edge_be = (const float*)d_in[19];
    float* out = (float*)d_out;

    knn_kernel<<<dim3(NN/256, NB), 256>>>(pos);
    prep_kernel<<<(NB*NN)/128, 128>>>(x, basis_W, edge_W, act_g, edge_g, edge_be);
    ap_tr_kernel<<<dim3(NN/32, NB), 256>>>(appf);
    glf_tr_kernel<<<dim3(NN/64, 32, NB), 256>>>(glf);

    const int smem_bytes = (128+16+512+32+2048+32+2048+64+4096 + 1024+2048+8192+4096 + 128) * (int)sizeof(float);
    cudaFuncSetAttribute(main_kernel, cudaFuncAttributeMaxDynamicSharedMemorySize, smem_bytes);
    main_kernel<<<NB*NN/128, 256, smem_bytes>>>(dk_W1, dk_b1, dk_g1, dk_be1,
                                                dk_W2, dk_b2, act_b,
                                                ff_W1, ff_g1, ff_be1, ff_W2,
                                                edge_W, edge_g, out);
}